// round 7
// baseline (speedup 1.0000x reference)
#include <cuda_runtime.h>
#include <cuda_bf16.h>

#define CC 256
#define HH 256
#define VV 10000
#define NB 8
#define TT 256
#define TM1 255

__device__ float g_h1[CC*HH];
__device__ float g_h2[CC*HH];
__device__ float g_slogit[CC];
__device__ float g_init[CC];
__device__ float g_tl[CC*CC];
__device__ float g_trans[CC*CC];     // log probs
__device__ float g_fwdM[CC*CC];      // [b][a] = exp(trans[a][b])
__device__ float g_bwdM[CC*CC];      // [a][b] = exp(trans[a][b])
__device__ float g_term[CC*VV];
__device__ float g_term_lse[CC];
__device__ float g_obs[NB*TT*CC];
__device__ float g_alphas[TM1*NB*CC];
__device__ float g_betas[TM1*NB*CC];
__device__ float g_logZ[NB];
__device__ float g_evidence;
__device__ float g_partials[1024];

__device__ __forceinline__ float blockMax256(float v, volatile float* red) {
    #pragma unroll
    for (int o = 16; o > 0; o >>= 1) v = fmaxf(v, __shfl_xor_sync(0xffffffffu, v, o));
    if ((threadIdx.x & 31) == 0) red[threadIdx.x >> 5] = v;
    __syncthreads();
    float r = red[0];
    #pragma unroll
    for (int i = 1; i < 8; ++i) r = fmaxf(r, red[i]);
    __syncthreads();
    return r;
}

__device__ __forceinline__ float blockSum256(float v, volatile float* red) {
    #pragma unroll
    for (int o = 16; o > 0; o >>= 1) v += __shfl_xor_sync(0xffffffffu, v, o);
    if ((threadIdx.x & 31) == 0) red[threadIdx.x >> 5] = v;
    __syncthreads();
    float r = red[0];
    #pragma unroll
    for (int i = 1; i < 8; ++i) r += red[i];
    __syncthreads();
    return r;
}

// C[256,N] = act(A[256,256] @ W[256,N] + bias) (+X). 64x64 tiles, 4x4 per thread.
template<bool RELU, bool RES>
__global__ void __launch_bounds__(256) gemm256(const float* __restrict__ A,
                                               const float* __restrict__ W,
                                               const float* __restrict__ bias,
                                               const float* __restrict__ X,
                                               float* __restrict__ Cout, int N) {
    __shared__ float As[16][68];
    __shared__ float Ws[16][68];
    const int m0 = blockIdx.y * 64;
    const int n0 = blockIdx.x * 64;
    const int tid = threadIdx.x;
    const int tx = tid & 15, ty = tid >> 4;
    float acc[4][4] = {};
    for (int k0 = 0; k0 < 256; k0 += 16) {
        #pragma unroll
        for (int i = tid; i < 1024; i += 256) {
            int mm = i >> 4, kk = i & 15;
            As[kk][mm] = A[(m0 + mm) * 256 + k0 + kk];
        }
        #pragma unroll
        for (int i = tid; i < 1024; i += 256) {
            int kk = i >> 6, nn = i & 63;
            int n = n0 + nn;
            Ws[kk][nn] = (n < N) ? W[(k0 + kk) * N + n] : 0.f;
        }
        __syncthreads();
        #pragma unroll
        for (int kk = 0; kk < 16; ++kk) {
            float4 av = *(const float4*)&As[kk][ty * 4];
            float4 bv = *(const float4*)&Ws[kk][tx * 4];
            float a[4] = {av.x, av.y, av.z, av.w};
            float b[4] = {bv.x, bv.y, bv.z, bv.w};
            #pragma unroll
            for (int i = 0; i < 4; ++i)
                #pragma unroll
                for (int j = 0; j < 4; ++j)
                    acc[i][j] = fmaf(a[i], b[j], acc[i][j]);
        }
        __syncthreads();
    }
    #pragma unroll
    for (int i = 0; i < 4; ++i) {
        int m = m0 + ty * 4 + i;
        #pragma unroll
        for (int j = 0; j < 4; ++j) {
            int n = n0 + tx * 4 + j;
            if (n < N) {
                float c = acc[i][j] + bias[n];
                if (RELU) c = fmaxf(c, 0.f);
                if (RES)  c += X[m * 256 + n];
                Cout[m * N + n] = c;
            }
        }
    }
}

__global__ void gemv1_kernel(const float* __restrict__ w3, const float* __restrict__ b3) {
    int m = threadIdx.x;
    float acc = 0.f;
    #pragma unroll 8
    for (int k = 0; k < HH; ++k) acc = fmaf(g_h2[m * HH + k], w3[k], acc);
    g_slogit[m] = acc + b3[0];
}

__global__ void init_softmax_kernel() {
    __shared__ float red[8];
    float v = g_slogit[threadIdx.x];
    float m = blockMax256(v, red);
    float s = blockSum256(__expf(v - m), red);
    g_init[threadIdx.x] = v - m - __logf(s);
}

__global__ void trans_softmax_kernel() {
    __shared__ float red[8];
    int a = blockIdx.x, b = threadIdx.x;
    float v = g_tl[a * CC + b];
    float m = blockMax256(v, red);
    float s = blockSum256(__expf(v - m), red);
    float lr = v - m - __logf(s);
    float ex = __expf(lr);
    g_trans[a * CC + b] = lr;
    g_bwdM[a * CC + b] = ex;
    g_fwdM[b * CC + a] = ex;
}

__global__ void term_lse_kernel() {
    __shared__ float red[8];
    int c = blockIdx.x;
    const float* row = g_term + (size_t)c * VV;
    float m = -1e30f;
    for (int j = threadIdx.x; j < VV; j += 256) m = fmaxf(m, row[j]);
    m = blockMax256(m, red);
    float s = 0.f;
    for (int j = threadIdx.x; j < VV; j += 256) s += __expf(row[j] - m);
    s = blockSum256(s, red);
    if (threadIdx.x == 0) g_term_lse[c] = m + __logf(s);
}

__global__ void obs_kernel(const int* __restrict__ text) {
    int nt = blockIdx.x;
    int tok = text[nt];
    int c = threadIdx.x;
    g_obs[nt * CC + c] = g_term[(size_t)c * VV + tok] - g_term_lse[c];
}

// One CTA per (n, dir). Thread groups: bg = tid>>6 (b subgroup), ai = tid&63 (4 outputs).
__global__ void __launch_bounds__(256) scan_kernel() {
    __shared__ float e[256];
    __shared__ float part[4 * 256];
    __shared__ float red[8];
    const int bx = blockIdx.x;
    const bool fwd = bx < 8;
    const int n = fwd ? bx : bx - 8;
    const int tid = threadIdx.x;
    const int bg = tid >> 6, ai = tid & 63;
    const float* M = fwd ? g_fwdM : g_bwdM;

    if (fwd) {
        float alpha = 0.f;
        for (int t = 0; t < TM1; ++t) {
            float v = (t == 0) ? (g_init[tid] + g_obs[(n * TT) * CC + tid]) : alpha;
            float m = blockMax256(v, red);
            e[tid] = __expf(v - m);
            __syncthreads();
            float4 acc = {0.f, 0.f, 0.f, 0.f};
            #pragma unroll 8
            for (int j = 0; j < 64; ++j) {
                int b = j * 4 + bg;
                float eb = e[b];
                float4 mv = *(const float4*)(M + b * 256 + ai * 4);
                acc.x = fmaf(mv.x, eb, acc.x);
                acc.y = fmaf(mv.y, eb, acc.y);
                acc.z = fmaf(mv.z, eb, acc.z);
                acc.w = fmaf(mv.w, eb, acc.w);
            }
            *(float4*)&part[bg * 256 + ai * 4] = acc;
            __syncthreads();
            float s = part[tid] + part[256 + tid] + part[512 + tid] + part[768 + tid];
            alpha = m + __logf(s) + g_obs[(n * TT + t + 1) * CC + tid];
            g_alphas[(t * NB + n) * CC + tid] = alpha;
            __syncthreads();
        }
    } else {
        float carry = 0.f;
        for (int t = TM1 - 1; t >= 0; --t) {
            g_betas[(t * NB + n) * CC + tid] = carry;
            if (t == 0) break;
            float w = g_obs[(n * TT + t + 1) * CC + tid] + carry;
            float m = blockMax256(w, red);
            e[tid] = __expf(w - m);
            __syncthreads();
            float4 acc = {0.f, 0.f, 0.f, 0.f};
            #pragma unroll 8
            for (int j = 0; j < 64; ++j) {
                int a = j * 4 + bg;
                float ea = e[a];
                float4 mv = *(const float4*)(M + a * 256 + ai * 4);
                acc.x = fmaf(mv.x, ea, acc.x);
                acc.y = fmaf(mv.y, ea, acc.y);
                acc.z = fmaf(mv.z, ea, acc.z);
                acc.w = fmaf(mv.w, ea, acc.w);
            }
            *(float4*)&part[bg * 256 + ai * 4] = acc;
            __syncthreads();
            float s = part[tid] + part[256 + tid] + part[512 + tid] + part[768 + tid];
            carry = m + __logf(s);
            __syncthreads();
        }
    }
}

__global__ void logz_ev_kernel(const int* __restrict__ lengths) {
    __shared__ float red[8];
    float ev = 0.f;
    for (int n = 0; n < NB; ++n) {
        float v = g_alphas[((TM1 - 1) * NB + n) * CC + threadIdx.x];
        float m = blockMax256(v, red);
        float s = blockSum256(__expf(v - m), red);
        if (threadIdx.x == 0) g_logZ[n] = m + __logf(s);
        int ti = lengths[n] - 1;
        if (ti < 0) ti = 0;
        if (ti > TM1 - 1) ti = TM1 - 1;
        float v2 = g_alphas[(ti * NB + n) * CC + threadIdx.x];
        float m2 = blockMax256(v2, red);
        float s2 = blockSum256(__expf(v2 - m2), red);
        ev += m2 + __logf(s2);
    }
    if (threadIdx.x == 0) g_evidence = ev;
}

// grid (32 t-chunks, 4 a-chunks of 64, 8 n), 256 threads (thread = b).
#define ELBO_SMEM ((64 * 256 + 256 + 256 + 64 + 64 + 8) * 4)
__global__ void __launch_bounds__(256) elbo_kernel() {
    extern __shared__ float smf[];
    float* Ts   = smf;
    float* vb   = Ts + 64 * 256;
    float* t0b  = vb + 256;
    float* obsA = t0b + 256;
    float* wa   = obsA + 64;
    float* red  = wa + 64;
    const int n = blockIdx.z;
    const int a0 = blockIdx.y * 64;
    const int tb = blockIdx.x * 8;
    const int b = threadIdx.x;

    for (int i = threadIdx.x; i < 64 * 256; i += 256)
        Ts[i] = g_trans[(a0 + (i >> 8)) * CC + (i & 255)];
    const float lz = g_logZ[n];
    float local = 0.f;

    for (int tt = 0; tt < 8; ++tt) {
        int t = tb + tt;
        if (t >= TM1) break;
        __syncthreads();
        float tz = (t == 0) ? (g_init[b] + g_obs[(n * TT) * CC + b]) : 0.f;
        float ap = (t == 0) ? 0.f : g_alphas[((t - 1) * NB + n) * CC + b];
        t0b[b] = tz;
        vb[b]  = ap + tz - lz;
        if (b < 64) {
            int a = a0 + b;
            float oa = g_obs[(n * TT + t + 1) * CC + a];
            obsA[b] = oa;
            wa[b] = g_betas[(t * NB + n) * CC + a] + oa;
        }
        __syncthreads();
        float vbb = vb[b], tzb = t0b[b];
        #pragma unroll 8
        for (int al = 0; al < 64; ++al) {
            float tr = Ts[al * 256 + b];
            float L  = tr + wa[al] + vbb;
            float ph = tr + obsA[al] + tzb;
            local += __expf(L) * ph;
        }
    }
    __syncthreads();
    float s = blockSum256(local, red);
    if (threadIdx.x == 0)
        g_partials[(blockIdx.z * 4 + blockIdx.y) * 32 + blockIdx.x] = s;
}

__global__ void finalize_kernel(float* __restrict__ out) {
    __shared__ float red[8];
    float s = 0.f;
    for (int i = threadIdx.x; i < 1024; i += 256) s += g_partials[i];
    s = blockSum256(s, red);
    if (threadIdx.x == 0) { out[0] = s; out[1] = g_evidence; }
}

extern "C" void kernel_launch(void* const* d_in, const int* in_sizes, int n_in,
                              void* d_out, int out_size) {
    const int*   text      = (const int*)d_in[0];
    const int*   lengths   = (const int*)d_in[2];
    const float* start_emb = (const float*)d_in[3];
    const float* state_emb = (const float*)d_in[4];
    const float* pre_emb   = (const float*)d_in[5];
    const float* sw1 = (const float*)d_in[6];
    const float* sb1 = (const float*)d_in[7];
    const float* sw2 = (const float*)d_in[8];
    const float* sb2 = (const float*)d_in[9];
    const float* sw3 = (const float*)d_in[10];
    const float* sb3 = (const float*)d_in[11];
    const float* tw1 = (const float*)d_in[12];
    const float* tb1 = (const float*)d_in[13];
    const float* tw2 = (const float*)d_in[14];
    const float* tb2 = (const float*)d_in[15];
    const float* tw3 = (const float*)d_in[16];
    const float* tb3 = (const float*)d_in[17];
    const float* ew1 = (const float*)d_in[18];
    const float* eb1 = (const float*)d_in[19];
    const float* ew2 = (const float*)d_in[20];
    const float* eb2 = (const float*)d_in[21];
    const float* ew3 = (const float*)d_in[22];
    const float* eb3 = (const float*)d_in[23];
    float* out = (float*)d_out;

    cudaFuncSetAttribute(elbo_kernel, cudaFuncAttributeMaxDynamicSharedMemorySize, ELBO_SMEM);

    void *p_h1, *p_h2, *p_tl, *p_term;
    cudaGetSymbolAddress(&p_h1, g_h1);
    cudaGetSymbolAddress(&p_h2, g_h2);
    cudaGetSymbolAddress(&p_tl, g_tl);
    cudaGetSymbolAddress(&p_term, g_term);
    float* h1   = (float*)p_h1;
    float* h2   = (float*)p_h2;
    float* tl   = (float*)p_tl;
    float* term = (float*)p_term;

    dim3 g44(4, 4);

    gemm256<true,  false><<<g44, 256>>>(start_emb, sw1, sb1, nullptr,   h1, 256);
    gemm256<true,  true ><<<g44, 256>>>(h1,        sw2, sb2, start_emb, h2, 256);
    gemv1_kernel<<<1, 256>>>(sw3, sb3);

    gemm256<true,  false><<<g44, 256>>>(state_emb, tw1, tb1, nullptr,   h1, 256);
    gemm256<true,  true ><<<g44, 256>>>(h1,        tw2, tb2, state_emb, h2, 256);
    gemm256<false, false><<<g44, 256>>>(h2,        tw3, tb3, nullptr,   tl, 256);

    gemm256<true,  false><<<g44, 256>>>(pre_emb,   ew1, eb1, nullptr,   h1, 256);
    gemm256<true,  true ><<<g44, 256>>>(h1,        ew2, eb2, pre_emb,   h2, 256);
    gemm256<false, false><<<dim3(157, 4), 256>>>(h2, ew3, eb3, nullptr, term, VV);

    init_softmax_kernel<<<1, 256>>>();
    trans_softmax_kernel<<<256, 256>>>();
    term_lse_kernel<<<256, 256>>>();
    obs_kernel<<<NB * TT, 256>>>(text);

    scan_kernel<<<16, 256>>>();
    logz_ev_kernel<<<1, 256>>>(lengths);

    elbo_kernel<<<dim3(32, 4, 8), 256, ELBO_SMEM>>>();
    finalize_kernel<<<1, 256>>>(out);
}

// round 12
// speedup vs baseline: 2.8095x; 2.8095x over previous
#include <cuda_runtime.h>
#include <cuda_fp16.h>

#define CC 256
#define HH 256
#define VV 10000
#define NB 8
#define TT 256
#define TM1 255
#define MROW 132   // half2 per smem matrix row (128 data + 4 pad) -> 528B stride

__device__ float g_h1[3*CC*HH];
__device__ float g_h2[3*CC*HH];
__device__ float g_slogit[CC];
__device__ float g_init[CC];
__device__ float g_tl[CC*CC];
__device__ float g_trans[CC*CC];     // log probs
__device__ float g_fwdM[CC*CC];      // [b][a] = exp(trans[a][b])  (bwd scan reads rows)
__device__ float g_bwdM[CC*CC];      // [a][b] = exp(trans[a][b])  (fwd scan reads rows)
__device__ float g_term[CC*VV];
__device__ float g_obs[NB*TT*CC];
__device__ float g_alphas[TM1*NB*CC];
__device__ float g_betas[TM1*NB*CC];
__device__ float g_logZ[NB];
__device__ float g_evidence;
__device__ float g_partials[1024];

__device__ __forceinline__ float blockMax256(float v, volatile float* red) {
    #pragma unroll
    for (int o = 16; o > 0; o >>= 1) v = fmaxf(v, __shfl_xor_sync(0xffffffffu, v, o));
    if ((threadIdx.x & 31) == 0) red[threadIdx.x >> 5] = v;
    __syncthreads();
    float r = red[0];
    #pragma unroll
    for (int i = 1; i < 8; ++i) r = fmaxf(r, red[i]);
    __syncthreads();
    return r;
}

__device__ __forceinline__ float blockSum256(float v, volatile float* red) {
    #pragma unroll
    for (int o = 16; o > 0; o >>= 1) v += __shfl_xor_sync(0xffffffffu, v, o);
    if ((threadIdx.x & 31) == 0) red[threadIdx.x >> 5] = v;
    __syncthreads();
    float r = red[0];
    #pragma unroll
    for (int i = 1; i < 8; ++i) r += red[i];
    __syncthreads();
    return r;
}

// 64x64 tile GEMM body: C[256,N] = act(A[256,256] @ W[256,N] + bias) (+X)
template<bool RELU, bool RES>
__device__ __forceinline__ void gemm_body(const float* __restrict__ A,
                                          const float* __restrict__ W,
                                          const float* __restrict__ bias,
                                          const float* __restrict__ X,
                                          float* __restrict__ Cout, int N) {
    __shared__ float As[16][68];
    __shared__ float Ws[16][68];
    const int m0 = blockIdx.y * 64;
    const int n0 = blockIdx.x * 64;
    const int tid = threadIdx.x;
    const int tx = tid & 15, ty = tid >> 4;
    float acc[4][4] = {};
    for (int k0 = 0; k0 < 256; k0 += 16) {
        #pragma unroll
        for (int i = tid; i < 1024; i += 256) {
            int mm = i >> 4, kk = i & 15;
            As[kk][mm] = A[(m0 + mm) * 256 + k0 + kk];
        }
        #pragma unroll
        for (int i = tid; i < 1024; i += 256) {
            int kk = i >> 6, nn = i & 63;
            int n = n0 + nn;
            Ws[kk][nn] = (n < N) ? W[(size_t)(k0 + kk) * N + n] : 0.f;
        }
        __syncthreads();
        #pragma unroll
        for (int kk = 0; kk < 16; ++kk) {
            float4 av = *(const float4*)&As[kk][ty * 4];
            float4 bv = *(const float4*)&Ws[kk][tx * 4];
            float a[4] = {av.x, av.y, av.z, av.w};
            float b[4] = {bv.x, bv.y, bv.z, bv.w};
            #pragma unroll
            for (int i = 0; i < 4; ++i)
                #pragma unroll
                for (int j = 0; j < 4; ++j)
                    acc[i][j] = fmaf(a[i], b[j], acc[i][j]);
        }
        __syncthreads();
    }
    #pragma unroll
    for (int i = 0; i < 4; ++i) {
        int m = m0 + ty * 4 + i;
        #pragma unroll
        for (int j = 0; j < 4; ++j) {
            int n = n0 + tx * 4 + j;
            if (n < N) {
                float c = acc[i][j] + bias[n];
                if (RELU) c = fmaxf(c, 0.f);
                if (RES)  c += X[m * 256 + n];
                Cout[(size_t)m * N + n] = c;
            }
        }
    }
}

// layer1 of all 3 nets: grid (4,4,3)
__global__ void __launch_bounds__(256) gemmL1_kernel(
    const float* A0, const float* A1, const float* A2,
    const float* W0, const float* W1, const float* W2,
    const float* b0, const float* b1, const float* b2) {
    int z = blockIdx.z;
    const float* A = (z == 0) ? A0 : (z == 1) ? A1 : A2;
    const float* W = (z == 0) ? W0 : (z == 1) ? W1 : W2;
    const float* b = (z == 0) ? b0 : (z == 1) ? b1 : b2;
    gemm_body<true, false>(A, W, b, nullptr, g_h1 + z * CC * HH, 256);
}

// layer2 of all 3 nets (relu + residual): grid (4,4,3)
__global__ void __launch_bounds__(256) gemmL2_kernel(
    const float* X0, const float* X1, const float* X2,
    const float* W0, const float* W1, const float* W2,
    const float* b0, const float* b1, const float* b2) {
    int z = blockIdx.z;
    const float* X = (z == 0) ? X0 : (z == 1) ? X1 : X2;
    const float* W = (z == 0) ? W0 : (z == 1) ? W1 : W2;
    const float* b = (z == 0) ? b0 : (z == 1) ? b1 : b2;
    gemm_body<true, true>(g_h1 + z * CC * HH, W, b, X, g_h2 + z * CC * HH, 256);
}

// heads: z=0 term (157x4 tiles), z=1 trans (4x4), z=2 start gemv. grid (157,4,3)
__global__ void __launch_bounds__(256) heads_kernel(
    const float* tw3, const float* tb3,
    const float* ew3, const float* eb3,
    const float* sw3, const float* sb3) {
    int z = blockIdx.z;
    if (z == 0) {
        gemm_body<false, false>(g_h2 + 2 * CC * HH, ew3, eb3, nullptr, g_term, VV);
    } else if (z == 1) {
        if (blockIdx.x >= 4) return;
        gemm_body<false, false>(g_h2 + 1 * CC * HH, tw3, tb3, nullptr, g_tl, 256);
    } else {
        if (blockIdx.x != 0 || blockIdx.y != 0) return;
        int m = threadIdx.x;
        float acc = 0.f;
        #pragma unroll 8
        for (int k = 0; k < HH; ++k) acc = fmaf(g_h2[m * HH + k], sw3[k], acc);
        g_slogit[m] = acc + sb3[0];
    }
}

__global__ void trans_softmax_kernel() {
    __shared__ float red[8];
    int a = blockIdx.x, b = threadIdx.x;
    float v = g_tl[a * CC + b];
    float m = blockMax256(v, red);
    float s = blockSum256(__expf(v - m), red);
    float lr = v - m - __logf(s);
    float ex = __expf(lr);
    g_trans[a * CC + b] = lr;
    g_bwdM[a * CC + b] = ex;
    g_fwdM[b * CC + a] = ex;
}

// grid 257: x<256 -> term lse + obs for state x; x==256 -> init softmax
__global__ void prepB_kernel(const int* __restrict__ text) {
    __shared__ float red[8];
    int x = blockIdx.x;
    if (x == 256) {
        float v = g_slogit[threadIdx.x];
        float m = blockMax256(v, red);
        float s = blockSum256(__expf(v - m), red);
        g_init[threadIdx.x] = v - m - __logf(s);
        return;
    }
    const float* row = g_term + (size_t)x * VV;
    float m = -1e30f;
    for (int j = threadIdx.x; j < VV; j += 256) m = fmaxf(m, row[j]);
    m = blockMax256(m, red);
    float s = 0.f;
    for (int j = threadIdx.x; j < VV; j += 256) s += __expf(row[j] - m);
    s = blockSum256(s, red);
    float lse = m + __logf(s);
    for (int nt = threadIdx.x; nt < NB * TT; nt += 256) {
        int tok = text[nt];
        g_obs[nt * CC + x] = row[tok] - lse;
    }
}

// One CTA per (n, dir). Matrix as half2 in smem, padded rows (4-phase LDS.128).
#define SCAN_SMEM (CC * MROW * 4)
__global__ void __launch_bounds__(256) scan_kernel() {
    extern __shared__ __half2 Mh[];      // [256][MROW]
    __shared__ float e[256];
    __shared__ float red[8];
    const int bx = blockIdx.x;
    const bool fwd = bx < 8;
    const int n = fwd ? bx : bx - 8;
    const int tid = threadIdx.x;
    const float* src = fwd ? g_bwdM : g_fwdM;   // row-major over summed index

    for (int idx = tid; idx < 256 * 128; idx += 256) {
        int row = idx >> 7, c2 = idx & 127;
        float2 v = *(const float2*)(src + row * 256 + c2 * 2);
        Mh[row * MROW + c2] = __floats2half2_rn(v.x, v.y);
    }
    __syncthreads();

    const uint4* Mrow = (const uint4*)(Mh + tid * MROW);
    const float4* ef4 = (const float4*)e;

    if (fwd) {
        float alpha = 0.f;
        for (int t = 0; t < TM1; ++t) {
            float v = (t == 0) ? (g_init[tid] + g_obs[(n * TT) * CC + tid]) : alpha;
            float m = blockMax256(v, red);
            e[tid] = __expf(v - m);
            __syncthreads();
            float a0 = 0.f, a1 = 0.f, a2 = 0.f, a3 = 0.f;
            #pragma unroll
            for (int i = 0; i < 32; ++i) {
                uint4 mw = Mrow[i];
                float4 e0 = ef4[2 * i], e1 = ef4[2 * i + 1];
                float2 f;
                f = __half22float2(*(const __half2*)&mw.x); a0 = fmaf(f.x, e0.x, a0); a1 = fmaf(f.y, e0.y, a1);
                f = __half22float2(*(const __half2*)&mw.y); a2 = fmaf(f.x, e0.z, a2); a3 = fmaf(f.y, e0.w, a3);
                f = __half22float2(*(const __half2*)&mw.z); a0 = fmaf(f.x, e1.x, a0); a1 = fmaf(f.y, e1.y, a1);
                f = __half22float2(*(const __half2*)&mw.w); a2 = fmaf(f.x, e1.z, a2); a3 = fmaf(f.y, e1.w, a3);
            }
            float s = (a0 + a1) + (a2 + a3);
            alpha = m + __logf(s) + g_obs[(n * TT + t + 1) * CC + tid];
            g_alphas[(t * NB + n) * CC + tid] = alpha;
            __syncthreads();
        }
    } else {
        float carry = 0.f;
        for (int t = TM1 - 1; t >= 0; --t) {
            g_betas[(t * NB + n) * CC + tid] = carry;
            if (t == 0) break;
            float w = g_obs[(n * TT + t + 1) * CC + tid] + carry;
            float m = blockMax256(w, red);
            e[tid] = __expf(w - m);
            __syncthreads();
            float a0 = 0.f, a1 = 0.f, a2 = 0.f, a3 = 0.f;
            #pragma unroll
            for (int i = 0; i < 32; ++i) {
                uint4 mw = Mrow[i];
                float4 e0 = ef4[2 * i], e1 = ef4[2 * i + 1];
                float2 f;
                f = __half22float2(*(const __half2*)&mw.x); a0 = fmaf(f.x, e0.x, a0); a1 = fmaf(f.y, e0.y, a1);
                f = __half22float2(*(const __half2*)&mw.y); a2 = fmaf(f.x, e0.z, a2); a3 = fmaf(f.y, e0.w, a3);
                f = __half22float2(*(const __half2*)&mw.z); a0 = fmaf(f.x, e1.x, a0); a1 = fmaf(f.y, e1.y, a1);
                f = __half22float2(*(const __half2*)&mw.w); a2 = fmaf(f.x, e1.z, a2); a3 = fmaf(f.y, e1.w, a3);
            }
            float s = (a0 + a1) + (a2 + a3);
            carry = m + __logf(s);
            __syncthreads();
        }
    }
}

__global__ void logz_ev_kernel(const int* __restrict__ lengths) {
    __shared__ float red[8];
    float ev = 0.f;
    for (int n = 0; n < NB; ++n) {
        float v = g_alphas[((TM1 - 1) * NB + n) * CC + threadIdx.x];
        float m = blockMax256(v, red);
        float s = blockSum256(__expf(v - m), red);
        if (threadIdx.x == 0) g_logZ[n] = m + __logf(s);
        int ti = lengths[n] - 1;
        if (ti < 0) ti = 0;
        if (ti > TM1 - 1) ti = TM1 - 1;
        float v2 = g_alphas[(ti * NB + n) * CC + threadIdx.x];
        float m2 = blockMax256(v2, red);
        float s2 = blockSum256(__expf(v2 - m2), red);
        ev += m2 + __logf(s2);
    }
    if (threadIdx.x == 0) g_evidence = ev;
}

#define ELBO_SMEM ((64 * 256 + 256 + 256 + 64 + 64 + 8) * 4)
__global__ void __launch_bounds__(256) elbo_kernel() {
    extern __shared__ float smf[];
    float* Ts   = smf;
    float* vb   = Ts + 64 * 256;
    float* t0b  = vb + 256;
    float* obsA = t0b + 256;
    float* wa   = obsA + 64;
    float* red  = wa + 64;
    const int n = blockIdx.z;
    const int a0 = blockIdx.y * 64;
    const int tb = blockIdx.x * 8;
    const int b = threadIdx.x;

    for (int i = threadIdx.x; i < 64 * 256; i += 256)
        Ts[i] = g_trans[(a0 + (i >> 8)) * CC + (i & 255)];
    const float lz = g_logZ[n];
    float local = 0.f;

    for (int tt = 0; tt < 8; ++tt) {
        int t = tb + tt;
        if (t >= TM1) break;
        __syncthreads();
        float tz = (t == 0) ? (g_init[b] + g_obs[(n * TT) * CC + b]) : 0.f;
        float ap = (t == 0) ? 0.f : g_alphas[((t - 1) * NB + n) * CC + b];
        t0b[b] = tz;
        vb[b]  = ap + tz - lz;
        if (b < 64) {
            int a = a0 + b;
            float oa = g_obs[(n * TT + t + 1) * CC + a];
            obsA[b] = oa;
            wa[b] = g_betas[(t * NB + n) * CC + a] + oa;
        }
        __syncthreads();
        float vbb = vb[b], tzb = t0b[b];
        #pragma unroll 8
        for (int al = 0; al < 64; ++al) {
            float tr = Ts[al * 256 + b];
            float L  = tr + wa[al] + vbb;
            float ph = tr + obsA[al] + tzb;
            local += __expf(L) * ph;
        }
    }
    __syncthreads();
    float s = blockSum256(local, red);
    if (threadIdx.x == 0)
        g_partials[(blockIdx.z * 4 + blockIdx.y) * 32 + blockIdx.x] = s;
}

__global__ void finalize_kernel(float* __restrict__ out) {
    __shared__ float red[8];
    float s = 0.f;
    for (int i = threadIdx.x; i < 1024; i += 256) s += g_partials[i];
    s = blockSum256(s, red);
    if (threadIdx.x == 0) { out[0] = s; out[1] = g_evidence; }
}

extern "C" void kernel_launch(void* const* d_in, const int* in_sizes, int n_in,
                              void* d_out, int out_size) {
    const int*   text      = (const int*)d_in[0];
    const int*   lengths   = (const int*)d_in[2];
    const float* start_emb = (const float*)d_in[3];
    const float* state_emb = (const float*)d_in[4];
    const float* pre_emb   = (const float*)d_in[5];
    const float* sw1 = (const float*)d_in[6];
    const float* sb1 = (const float*)d_in[7];
    const float* sw2 = (const float*)d_in[8];
    const float* sb2 = (const float*)d_in[9];
    const float* sw3 = (const float*)d_in[10];
    const float* sb3 = (const float*)d_in[11];
    const float* tw1 = (const float*)d_in[12];
    const float* tb1 = (const float*)d_in[13];
    const float* tw2 = (const float*)d_in[14];
    const float* tb2 = (const float*)d_in[15];
    const float* tw3 = (const float*)d_in[16];
    const float* tb3 = (const float*)d_in[17];
    const float* ew1 = (const float*)d_in[18];
    const float* eb1 = (const float*)d_in[19];
    const float* ew2 = (const float*)d_in[20];
    const float* eb2 = (const float*)d_in[21];
    const float* ew3 = (const float*)d_in[22];
    const float* eb3 = (const float*)d_in[23];
    float* out = (float*)d_out;

    cudaFuncSetAttribute(scan_kernel, cudaFuncAttributeMaxDynamicSharedMemorySize, SCAN_SMEM);
    cudaFuncSetAttribute(elbo_kernel, cudaFuncAttributeMaxDynamicSharedMemorySize, ELBO_SMEM);

    // launch 0: layer1 of start/trans/term nets
    gemmL1_kernel<<<dim3(4, 4, 3), 256>>>(start_emb, state_emb, pre_emb,
                                          sw1, tw1, ew1, sb1, tb1, eb1);
    // launch 1: layer2 (relu + residual)
    gemmL2_kernel<<<dim3(4, 4, 3), 256>>>(start_emb, state_emb, pre_emb,
                                          sw2, tw2, ew2, sb2, tb2, eb2);
    // launch 2: heads (term GEMM + trans GEMM + start gemv)
    heads_kernel<<<dim3(157, 4, 3), 256>>>(tw3, tb3, ew3, eb3, sw3, sb3);
    // launch 3: transition softmax -> log probs + exp matrices (both layouts)
    trans_softmax_kernel<<<256, 256>>>();
    // launch 4: term lse + obs gather + init softmax
    prepB_kernel<<<257, 256>>>(text);
    // launch 5: forward/backward scans (profiled by ncu -s 5 -c 1)
    scan_kernel<<<16, 256, SCAN_SMEM>>>();
    // launch 6: logZ + evidence
    logz_ev_kernel<<<1, 256>>>(lengths);
    // launch 7: elbo accumulation
    elbo_kernel<<<dim3(32, 4, 8), 256, ELBO_SMEM>>>();
    // launch 8: final reduction
    finalize_kernel<<<1, 256>>>(out);
}

// round 15
// speedup vs baseline: 3.9268x; 1.3977x over previous
#include <cuda_runtime.h>
#include <cuda_fp16.h>

#define CC 256
#define HH 256
#define VV 10000
#define NB 8
#define TT 256
#define TM1 255

__device__ float g_h1[3*CC*HH];
__device__ float g_h2[3*CC*HH];
__device__ float g_slogit[CC];
__device__ float g_init[CC];
__device__ float g_tl[CC*CC];
__device__ float g_trans[CC*CC];     // log probs
__device__ float g_fwdM[CC*CC];      // [b][a] = exp(trans[a][b])  (bwd scan rows)
__device__ float g_bwdM[CC*CC];      // [a][b] = exp(trans[a][b])  (fwd scan rows)
__device__ float g_term[CC*VV];
__device__ float g_obs[NB*TT*CC];
__device__ float g_alphas[TM1*NB*CC];
__device__ float g_betas[TM1*NB*CC];
__device__ float g_logZ[NB];
__device__ float g_evidence;
__device__ float g_partials[1024];

__device__ __forceinline__ float blockMax256(float v, volatile float* red) {
    #pragma unroll
    for (int o = 16; o > 0; o >>= 1) v = fmaxf(v, __shfl_xor_sync(0xffffffffu, v, o));
    if ((threadIdx.x & 31) == 0) red[threadIdx.x >> 5] = v;
    __syncthreads();
    float r = red[0];
    #pragma unroll
    for (int i = 1; i < 8; ++i) r = fmaxf(r, red[i]);
    __syncthreads();
    return r;
}

__device__ __forceinline__ float blockSum256(float v, volatile float* red) {
    #pragma unroll
    for (int o = 16; o > 0; o >>= 1) v += __shfl_xor_sync(0xffffffffu, v, o);
    if ((threadIdx.x & 31) == 0) red[threadIdx.x >> 5] = v;
    __syncthreads();
    float r = red[0];
    #pragma unroll
    for (int i = 1; i < 8; ++i) r += red[i];
    __syncthreads();
    return r;
}

// 64x64 tile GEMM body: C[256,N] = act(A[256,256] @ W[256,N] + bias) (+X)
template<bool RELU, bool RES>
__device__ __forceinline__ void gemm_body(const float* __restrict__ A,
                                          const float* __restrict__ W,
                                          const float* __restrict__ bias,
                                          const float* __restrict__ X,
                                          float* __restrict__ Cout, int N) {
    __shared__ float As[16][68];
    __shared__ float Ws[16][68];
    const int m0 = blockIdx.y * 64;
    const int n0 = blockIdx.x * 64;
    const int tid = threadIdx.x;
    const int tx = tid & 15, ty = tid >> 4;
    float acc[4][4] = {};
    for (int k0 = 0; k0 < 256; k0 += 16) {
        #pragma unroll
        for (int i = tid; i < 1024; i += 256) {
            int mm = i >> 4, kk = i & 15;
            As[kk][mm] = A[(m0 + mm) * 256 + k0 + kk];
        }
        #pragma unroll
        for (int i = tid; i < 1024; i += 256) {
            int kk = i >> 6, nn = i & 63;
            int n = n0 + nn;
            Ws[kk][nn] = (n < N) ? W[(size_t)(k0 + kk) * N + n] : 0.f;
        }
        __syncthreads();
        #pragma unroll
        for (int kk = 0; kk < 16; ++kk) {
            float4 av = *(const float4*)&As[kk][ty * 4];
            float4 bv = *(const float4*)&Ws[kk][tx * 4];
            float a[4] = {av.x, av.y, av.z, av.w};
            float b[4] = {bv.x, bv.y, bv.z, bv.w};
            #pragma unroll
            for (int i = 0; i < 4; ++i)
                #pragma unroll
                for (int j = 0; j < 4; ++j)
                    acc[i][j] = fmaf(a[i], b[j], acc[i][j]);
        }
        __syncthreads();
    }
    #pragma unroll
    for (int i = 0; i < 4; ++i) {
        int m = m0 + ty * 4 + i;
        #pragma unroll
        for (int j = 0; j < 4; ++j) {
            int n = n0 + tx * 4 + j;
            if (n < N) {
                float c = acc[i][j] + bias[n];
                if (RELU) c = fmaxf(c, 0.f);
                if (RES)  c += X[m * 256 + n];
                Cout[(size_t)m * N + n] = c;
            }
        }
    }
}

__global__ void __launch_bounds__(256) gemmL1_kernel(
    const float* A0, const float* A1, const float* A2,
    const float* W0, const float* W1, const float* W2,
    const float* b0, const float* b1, const float* b2) {
    int z = blockIdx.z;
    const float* A = (z == 0) ? A0 : (z == 1) ? A1 : A2;
    const float* W = (z == 0) ? W0 : (z == 1) ? W1 : W2;
    const float* b = (z == 0) ? b0 : (z == 1) ? b1 : b2;
    gemm_body<true, false>(A, W, b, nullptr, g_h1 + z * CC * HH, 256);
}

__global__ void __launch_bounds__(256) gemmL2_kernel(
    const float* X0, const float* X1, const float* X2,
    const float* W0, const float* W1, const float* W2,
    const float* b0, const float* b1, const float* b2) {
    int z = blockIdx.z;
    const float* X = (z == 0) ? X0 : (z == 1) ? X1 : X2;
    const float* W = (z == 0) ? W0 : (z == 1) ? W1 : W2;
    const float* b = (z == 0) ? b0 : (z == 1) ? b1 : b2;
    gemm_body<true, true>(g_h1 + z * CC * HH, W, b, X, g_h2 + z * CC * HH, 256);
}

// heads: z=0 term (157x4 tiles), z=1 trans (4x4), z=2 start gemv. grid (157,4,3)
__global__ void __launch_bounds__(256) heads_kernel(
    const float* tw3, const float* tb3,
    const float* ew3, const float* eb3,
    const float* sw3, const float* sb3) {
    int z = blockIdx.z;
    if (z == 0) {
        gemm_body<false, false>(g_h2 + 2 * CC * HH, ew3, eb3, nullptr, g_term, VV);
    } else if (z == 1) {
        if (blockIdx.x >= 4) return;
        gemm_body<false, false>(g_h2 + 1 * CC * HH, tw3, tb3, nullptr, g_tl, 256);
    } else {
        if (blockIdx.x != 0 || blockIdx.y != 0) return;
        int m = threadIdx.x;
        float acc = 0.f;
        #pragma unroll 8
        for (int k = 0; k < HH; ++k) acc = fmaf(g_h2[m * HH + k], sw3[k], acc);
        g_slogit[m] = acc + sb3[0];
    }
}

__global__ void trans_softmax_kernel() {
    __shared__ float red[8];
    int a = blockIdx.x, b = threadIdx.x;
    float v = g_tl[a * CC + b];
    float m = blockMax256(v, red);
    float s = blockSum256(__expf(v - m), red);
    float lr = v - m - __logf(s);
    float ex = __expf(lr);
    g_trans[a * CC + b] = lr;
    g_bwdM[a * CC + b] = ex;
    g_fwdM[b * CC + a] = ex;
}

// grid 257: x<256 -> term lse + obs for state x; x==256 -> init softmax
__global__ void prepB_kernel(const int* __restrict__ text) {
    __shared__ float red[8];
    int x = blockIdx.x;
    if (x == 256) {
        float v = g_slogit[threadIdx.x];
        float m = blockMax256(v, red);
        float s = blockSum256(__expf(v - m), red);
        g_init[threadIdx.x] = v - m - __logf(s);
        return;
    }
    const float* row = g_term + (size_t)x * VV;
    float m = -1e30f;
    for (int j = threadIdx.x; j < VV; j += 256) m = fmaxf(m, row[j]);
    m = blockMax256(m, red);
    float s = 0.f;
    for (int j = threadIdx.x; j < VV; j += 256) s += __expf(row[j] - m);
    s = blockSum256(s, red);
    float lse = m + __logf(s);
    for (int nt = threadIdx.x; nt < NB * TT; nt += 256) {
        int tok = text[nt];
        g_obs[nt * CC + x] = row[tok] - lse;
    }
}

// ---- HMMA m16n8k16 helper (fp16 in, fp32 accum) ----
__device__ __forceinline__ void mma16816(float d[4], const unsigned a[4], const unsigned b[2]) {
    asm volatile(
        "mma.sync.aligned.m16n8k16.row.col.f32.f16.f16.f32 "
        "{%0,%1,%2,%3}, {%4,%5,%6,%7}, {%8,%9}, {%0,%1,%2,%3};"
        : "+f"(d[0]), "+f"(d[1]), "+f"(d[2]), "+f"(d[3])
        : "r"(a[0]), "r"(a[1]), "r"(a[2]), "r"(a[3]), "r"(b[0]), "r"(b[1]));
}

__device__ __forceinline__ unsigned pack_h2(float x, float y) {
    __half2 h = __floats2half2_rn(x, y);
    return *(unsigned*)&h;
}

// Tensor-core scan: one CTA per (n, dir). Transition matrix lives in A-fragments
// (registers) for all 255 steps; per step only the exp-vector moves through smem.
__global__ void __launch_bounds__(256) scan_kernel() {
    __shared__ __half e_h[CC];
    __shared__ float newv[CC];
    __shared__ float red[8];
    const int bx = blockIdx.x;
    const bool fwd = bx < 8;
    const int n = fwd ? bx : bx - 8;
    const int tid = threadIdx.x;
    const int w = tid >> 5, l = tid & 31;
    const int r = l >> 2, c = (l & 3) * 2;
    const float* M = fwd ? g_bwdM : g_fwdM;  // [row=output][col=summed]

    // Load A fragments once: warp w owns rows [32w, 32w+32), 2 row-tiles x 16 k-tiles.
    unsigned Af[2][16][4];
    #pragma unroll
    for (int rt = 0; rt < 2; ++rt) {
        #pragma unroll
        for (int kt = 0; kt < 16; ++kt) {
            int R = 32 * w + 16 * rt + r;
            int K = 16 * kt + c;
            float2 v00 = *(const float2*)(M + R * 256 + K);
            float2 v10 = *(const float2*)(M + (R + 8) * 256 + K);
            float2 v01 = *(const float2*)(M + R * 256 + K + 8);
            float2 v11 = *(const float2*)(M + (R + 8) * 256 + K + 8);
            Af[rt][kt][0] = pack_h2(v00.x, v00.y);
            Af[rt][kt][1] = pack_h2(v10.x, v10.y);
            Af[rt][kt][2] = pack_h2(v01.x, v01.y);
            Af[rt][kt][3] = pack_h2(v11.x, v11.y);
        }
    }
    __syncthreads();

    if (fwd) {
        float alpha = 0.f;
        for (int t = 0; t < TM1; ++t) {
            float obs_next = g_obs[(n * TT + t + 1) * CC + tid];
            float v = (t == 0) ? (g_init[tid] + g_obs[(n * TT) * CC + tid]) : alpha;
            float m = blockMax256(v, red);
            e_h[tid] = __float2half(__expf(v - m));
            __syncthreads();
            float d0[4] = {0.f, 0.f, 0.f, 0.f};
            float d1[4] = {0.f, 0.f, 0.f, 0.f};
            #pragma unroll
            for (int kt = 0; kt < 16; ++kt) {
                unsigned b[2];
                b[0] = *(const unsigned*)&e_h[16 * kt + c];
                b[1] = *(const unsigned*)&e_h[16 * kt + c + 8];
                mma16816(d0, Af[0][kt], b);
                mma16816(d1, Af[1][kt], b);
            }
            if ((l & 3) == 0) {
                newv[32 * w + r]      = d0[0];
                newv[32 * w + r + 8]  = d0[2];
                newv[32 * w + 16 + r] = d1[0];
                newv[32 * w + 24 + r] = d1[2];
            }
            __syncthreads();
            alpha = m + __logf(newv[tid]) + obs_next;
            g_alphas[(t * NB + n) * CC + tid] = alpha;
        }
    } else {
        float carry = 0.f;
        for (int t = TM1 - 1; t >= 0; --t) {
            g_betas[(t * NB + n) * CC + tid] = carry;
            if (t == 0) break;
            float wv = g_obs[(n * TT + t + 1) * CC + tid] + carry;
            float m = blockMax256(wv, red);
            e_h[tid] = __float2half(__expf(wv - m));
            __syncthreads();
            float d0[4] = {0.f, 0.f, 0.f, 0.f};
            float d1[4] = {0.f, 0.f, 0.f, 0.f};
            #pragma unroll
            for (int kt = 0; kt < 16; ++kt) {
                unsigned b[2];
                b[0] = *(const unsigned*)&e_h[16 * kt + c];
                b[1] = *(const unsigned*)&e_h[16 * kt + c + 8];
                mma16816(d0, Af[0][kt], b);
                mma16816(d1, Af[1][kt], b);
            }
            if ((l & 3) == 0) {
                newv[32 * w + r]      = d0[0];
                newv[32 * w + r + 8]  = d0[2];
                newv[32 * w + 16 + r] = d1[0];
                newv[32 * w + 24 + r] = d1[2];
            }
            __syncthreads();
            carry = m + __logf(newv[tid]);
        }
    }
}

__global__ void logz_ev_kernel(const int* __restrict__ lengths) {
    __shared__ float red[8];
    float ev = 0.f;
    for (int n = 0; n < NB; ++n) {
        float v = g_alphas[((TM1 - 1) * NB + n) * CC + threadIdx.x];
        float m = blockMax256(v, red);
        float s = blockSum256(__expf(v - m), red);
        if (threadIdx.x == 0) g_logZ[n] = m + __logf(s);
        int ti = lengths[n] - 1;
        if (ti < 0) ti = 0;
        if (ti > TM1 - 1) ti = TM1 - 1;
        float v2 = g_alphas[(ti * NB + n) * CC + threadIdx.x];
        float m2 = blockMax256(v2, red);
        float s2 = blockSum256(__expf(v2 - m2), red);
        ev += m2 + __logf(s2);
    }
    if (threadIdx.x == 0) g_evidence = ev;
}

#define ELBO_SMEM ((64 * 256 + 256 + 256 + 64 + 64 + 8) * 4)
__global__ void __launch_bounds__(256) elbo_kernel() {
    extern __shared__ float smf[];
    float* Ts   = smf;
    float* vb   = Ts + 64 * 256;
    float* t0b  = vb + 256;
    float* obsA = t0b + 256;
    float* wa   = obsA + 64;
    float* red  = wa + 64;
    const int n = blockIdx.z;
    const int a0 = blockIdx.y * 64;
    const int tb = blockIdx.x * 8;
    const int b = threadIdx.x;

    for (int i = threadIdx.x; i < 64 * 256; i += 256)
        Ts[i] = g_trans[(a0 + (i >> 8)) * CC + (i & 255)];
    const float lz = g_logZ[n];
    float local = 0.f;

    for (int tt = 0; tt < 8; ++tt) {
        int t = tb + tt;
        if (t >= TM1) break;
        __syncthreads();
        float tz = (t == 0) ? (g_init[b] + g_obs[(n * TT) * CC + b]) : 0.f;
        float ap = (t == 0) ? 0.f : g_alphas[((t - 1) * NB + n) * CC + b];
        t0b[b] = tz;
        vb[b]  = ap + tz - lz;
        if (b < 64) {
            int a = a0 + b;
            float oa = g_obs[(n * TT + t + 1) * CC + a];
            obsA[b] = oa;
            wa[b] = g_betas[(t * NB + n) * CC + a] + oa;
        }
        __syncthreads();
        float vbb = vb[b], tzb = t0b[b];
        #pragma unroll 8
        for (int al = 0; al < 64; ++al) {
            float tr = Ts[al * 256 + b];
            float L  = tr + wa[al] + vbb;
            float ph = tr + obsA[al] + tzb;
            local += __expf(L) * ph;
        }
    }
    __syncthreads();
    float s = blockSum256(local, red);
    if (threadIdx.x == 0)
        g_partials[(blockIdx.z * 4 + blockIdx.y) * 32 + blockIdx.x] = s;
}

__global__ void finalize_kernel(float* __restrict__ out) {
    __shared__ float red[8];
    float s = 0.f;
    for (int i = threadIdx.x; i < 1024; i += 256) s += g_partials[i];
    s = blockSum256(s, red);
    if (threadIdx.x == 0) { out[0] = s; out[1] = g_evidence; }
}

extern "C" void kernel_launch(void* const* d_in, const int* in_sizes, int n_in,
                              void* d_out, int out_size) {
    const int*   text      = (const int*)d_in[0];
    const int*   lengths   = (const int*)d_in[2];
    const float* start_emb = (const float*)d_in[3];
    const float* state_emb = (const float*)d_in[4];
    const float* pre_emb   = (const float*)d_in[5];
    const float* sw1 = (const float*)d_in[6];
    const float* sb1 = (const float*)d_in[7];
    const float* sw2 = (const float*)d_in[8];
    const float* sb2 = (const float*)d_in[9];
    const float* sw3 = (const float*)d_in[10];
    const float* sb3 = (const float*)d_in[11];
    const float* tw1 = (const float*)d_in[12];
    const float* tb1 = (const float*)d_in[13];
    const float* tw2 = (const float*)d_in[14];
    const float* tb2 = (const float*)d_in[15];
    const float* tw3 = (const float*)d_in[16];
    const float* tb3 = (const float*)d_in[17];
    const float* ew1 = (const float*)d_in[18];
    const float* eb1 = (const float*)d_in[19];
    const float* ew2 = (const float*)d_in[20];
    const float* eb2 = (const float*)d_in[21];
    const float* ew3 = (const float*)d_in[22];
    const float* eb3 = (const float*)d_in[23];
    float* out = (float*)d_out;

    cudaFuncSetAttribute(elbo_kernel, cudaFuncAttributeMaxDynamicSharedMemorySize, ELBO_SMEM);

    // launch 0: layer1 of start/trans/term nets
    gemmL1_kernel<<<dim3(4, 4, 3), 256>>>(start_emb, state_emb, pre_emb,
                                          sw1, tw1, ew1, sb1, tb1, eb1);
    // launch 1: layer2 (relu + residual)
    gemmL2_kernel<<<dim3(4, 4, 3), 256>>>(start_emb, state_emb, pre_emb,
                                          sw2, tw2, ew2, sb2, tb2, eb2);
    // launch 2: heads (term GEMM + trans GEMM + start gemv)
    heads_kernel<<<dim3(157, 4, 3), 256>>>(tw3, tb3, ew3, eb3, sw3, sb3);
    // launch 3: transition softmax -> log probs + exp matrices (both layouts)
    trans_softmax_kernel<<<256, 256>>>();
    // launch 4: term lse + obs gather + init softmax
    prepB_kernel<<<257, 256>>>(text);
    // launch 5: tensor-core forward/backward scans
    scan_kernel<<<16, 256>>>();
    // launch 6: logZ + evidence
    logz_ev_kernel<<<1, 256>>>(lengths);
    // launch 7: elbo accumulation
    elbo_kernel<<<dim3(32, 4, 8), 256, ELBO_SMEM>>>();
    // launch 8: final reduction
    finalize_kernel<<<1, 256>>>(out);
}

// round 16
// speedup vs baseline: 4.0340x; 1.0273x over previous
#include <cuda_runtime.h>
#include <cuda_fp16.h>

#define CC 256
#define HH 256
#define VV 10000
#define NB 8
#define TT 256
#define TM1 255

__device__ float g_h1[3*CC*HH];
__device__ float g_h2[3*CC*HH];
__device__ float g_slogit[CC];
__device__ float g_init[CC];
__device__ float g_tl[CC*CC];
__device__ float g_trans[CC*CC];     // log probs
__device__ float g_fwdM[CC*CC];      // [b][a] = exp(trans[a][b])  (bwd scan rows)
__device__ float g_bwdM[CC*CC];      // [a][b] = exp(trans[a][b])  (fwd scan rows)
__device__ float g_term[CC*VV];
__device__ float g_obs[NB*TT*CC];
__device__ float g_alphas[TM1*NB*CC];
__device__ float g_betas[TM1*NB*CC];
__device__ float g_logZ[NB];
__device__ float g_evidence;
__device__ float g_partials[1024];

__device__ __forceinline__ float blockMax256(float v, volatile float* red) {
    #pragma unroll
    for (int o = 16; o > 0; o >>= 1) v = fmaxf(v, __shfl_xor_sync(0xffffffffu, v, o));
    if ((threadIdx.x & 31) == 0) red[threadIdx.x >> 5] = v;
    __syncthreads();
    float r = red[0];
    #pragma unroll
    for (int i = 1; i < 8; ++i) r = fmaxf(r, red[i]);
    __syncthreads();
    return r;
}

__device__ __forceinline__ float blockSum256(float v, volatile float* red) {
    #pragma unroll
    for (int o = 16; o > 0; o >>= 1) v += __shfl_xor_sync(0xffffffffu, v, o);
    if ((threadIdx.x & 31) == 0) red[threadIdx.x >> 5] = v;
    __syncthreads();
    float r = red[0];
    #pragma unroll
    for (int i = 1; i < 8; ++i) r += red[i];
    __syncthreads();
    return r;
}

// Fast block max via redux.sync (ONE barrier). Caller must guarantee >=2 barriers
// between successive calls that share 'redu' (true in the scan loop).
__device__ __forceinline__ float blockMaxFast(float v, volatile unsigned* redu) {
    int s = __float_as_int(v);
    unsigned k = (unsigned)s ^ (unsigned)((s >> 31) | 0x80000000);
    asm volatile("redux.sync.max.u32 %0, %0, 0xffffffff;" : "+r"(k));
    if ((threadIdx.x & 31) == 0) redu[threadIdx.x >> 5] = k;
    __syncthreads();
    unsigned km = redu[0];
    #pragma unroll
    for (int i = 1; i < 8; ++i) { unsigned x = redu[i]; km = (x > km) ? x : km; }
    int sm = (km & 0x80000000u) ? (int)(km ^ 0x80000000u) : (int)~km;
    return __int_as_float(sm);
}

// 64x64 tile GEMM body: C[256,N] = act(A[256,256] @ W[256,N] + bias) (+X)
template<bool RELU, bool RES>
__device__ __forceinline__ void gemm_body(const float* __restrict__ A,
                                          const float* __restrict__ W,
                                          const float* __restrict__ bias,
                                          const float* __restrict__ X,
                                          float* __restrict__ Cout, int N) {
    __shared__ float As[16][68];
    __shared__ float Ws[16][68];
    const int m0 = blockIdx.y * 64;
    const int n0 = blockIdx.x * 64;
    const int tid = threadIdx.x;
    const int tx = tid & 15, ty = tid >> 4;
    float acc[4][4] = {};
    for (int k0 = 0; k0 < 256; k0 += 16) {
        #pragma unroll
        for (int i = tid; i < 1024; i += 256) {
            int mm = i >> 4, kk = i & 15;
            As[kk][mm] = A[(m0 + mm) * 256 + k0 + kk];
        }
        #pragma unroll
        for (int i = tid; i < 1024; i += 256) {
            int kk = i >> 6, nn = i & 63;
            int n = n0 + nn;
            Ws[kk][nn] = (n < N) ? W[(size_t)(k0 + kk) * N + n] : 0.f;
        }
        __syncthreads();
        #pragma unroll
        for (int kk = 0; kk < 16; ++kk) {
            float4 av = *(const float4*)&As[kk][ty * 4];
            float4 bv = *(const float4*)&Ws[kk][tx * 4];
            float a[4] = {av.x, av.y, av.z, av.w};
            float b[4] = {bv.x, bv.y, bv.z, bv.w};
            #pragma unroll
            for (int i = 0; i < 4; ++i)
                #pragma unroll
                for (int j = 0; j < 4; ++j)
                    acc[i][j] = fmaf(a[i], b[j], acc[i][j]);
        }
        __syncthreads();
    }
    #pragma unroll
    for (int i = 0; i < 4; ++i) {
        int m = m0 + ty * 4 + i;
        #pragma unroll
        for (int j = 0; j < 4; ++j) {
            int n = n0 + tx * 4 + j;
            if (n < N) {
                float c = acc[i][j] + bias[n];
                if (RELU) c = fmaxf(c, 0.f);
                if (RES)  c += X[m * 256 + n];
                Cout[(size_t)m * N + n] = c;
            }
        }
    }
}

__global__ void __launch_bounds__(256) gemmL1_kernel(
    const float* A0, const float* A1, const float* A2,
    const float* W0, const float* W1, const float* W2,
    const float* b0, const float* b1, const float* b2) {
    int z = blockIdx.z;
    const float* A = (z == 0) ? A0 : (z == 1) ? A1 : A2;
    const float* W = (z == 0) ? W0 : (z == 1) ? W1 : W2;
    const float* b = (z == 0) ? b0 : (z == 1) ? b1 : b2;
    gemm_body<true, false>(A, W, b, nullptr, g_h1 + z * CC * HH, 256);
}

__global__ void __launch_bounds__(256) gemmL2_kernel(
    const float* X0, const float* X1, const float* X2,
    const float* W0, const float* W1, const float* W2,
    const float* b0, const float* b1, const float* b2) {
    int z = blockIdx.z;
    const float* X = (z == 0) ? X0 : (z == 1) ? X1 : X2;
    const float* W = (z == 0) ? W0 : (z == 1) ? W1 : W2;
    const float* b = (z == 0) ? b0 : (z == 1) ? b1 : b2;
    gemm_body<true, true>(g_h1 + z * CC * HH, W, b, X, g_h2 + z * CC * HH, 256);
}

// heads: z=0 term (157x4 tiles), z=1 trans (4x4), z=2 start gemv. grid (157,4,3)
__global__ void __launch_bounds__(256) heads_kernel(
    const float* tw3, const float* tb3,
    const float* ew3, const float* eb3,
    const float* sw3, const float* sb3) {
    int z = blockIdx.z;
    if (z == 0) {
        gemm_body<false, false>(g_h2 + 2 * CC * HH, ew3, eb3, nullptr, g_term, VV);
    } else if (z == 1) {
        if (blockIdx.x >= 4) return;
        gemm_body<false, false>(g_h2 + 1 * CC * HH, tw3, tb3, nullptr, g_tl, 256);
    } else {
        if (blockIdx.x != 0 || blockIdx.y != 0) return;
        int m = threadIdx.x;
        float acc = 0.f;
        #pragma unroll 8
        for (int k = 0; k < HH; ++k) acc = fmaf(g_h2[m * HH + k], sw3[k], acc);
        g_slogit[m] = acc + sb3[0];
    }
}

// fused prep: x<256 -> trans softmax row x; 256<=x<512 -> term lse + obs for
// state x-256; x==512 -> init softmax
__global__ void prep_kernel(const int* __restrict__ text) {
    __shared__ float red[8];
    int x = blockIdx.x;
    if (x < 256) {
        int a = x, b = threadIdx.x;
        float v = g_tl[a * CC + b];
        float m = blockMax256(v, red);
        float s = blockSum256(__expf(v - m), red);
        float lr = v - m - __logf(s);
        float ex = __expf(lr);
        g_trans[a * CC + b] = lr;
        g_bwdM[a * CC + b] = ex;
        g_fwdM[b * CC + a] = ex;
        return;
    }
    if (x == 512) {
        float v = g_slogit[threadIdx.x];
        float m = blockMax256(v, red);
        float s = blockSum256(__expf(v - m), red);
        g_init[threadIdx.x] = v - m - __logf(s);
        return;
    }
    int st = x - 256;
    const float* row = g_term + (size_t)st * VV;
    float m = -1e30f;
    for (int j = threadIdx.x; j < VV; j += 256) m = fmaxf(m, row[j]);
    m = blockMax256(m, red);
    float s = 0.f;
    for (int j = threadIdx.x; j < VV; j += 256) s += __expf(row[j] - m);
    s = blockSum256(s, red);
    float lse = m + __logf(s);
    for (int nt = threadIdx.x; nt < NB * TT; nt += 256) {
        int tok = text[nt];
        g_obs[nt * CC + st] = row[tok] - lse;
    }
}

// ---- HMMA m16n8k16 helper (fp16 in, fp32 accum) ----
__device__ __forceinline__ void mma16816(float d[4], const unsigned a[4], const unsigned b[2]) {
    asm volatile(
        "mma.sync.aligned.m16n8k16.row.col.f32.f16.f16.f32 "
        "{%0,%1,%2,%3}, {%4,%5,%6,%7}, {%8,%9}, {%0,%1,%2,%3};"
        : "+f"(d[0]), "+f"(d[1]), "+f"(d[2]), "+f"(d[3])
        : "r"(a[0]), "r"(a[1]), "r"(a[2]), "r"(a[3]), "r"(b[0]), "r"(b[1]));
}

__device__ __forceinline__ unsigned pack_h2(float x, float y) {
    __half2 h = __floats2half2_rn(x, y);
    return *(unsigned*)&h;
}

// One matvec step: 4 independent accumulator chains (depth 8 each), results for
// this warp's 32 rows written to newv by the (l&3)==0 lanes.
__device__ __forceinline__ void mma_step(const unsigned Af[2][16][4],
                                         const __half* e_h, float* newv,
                                         int w, int r, int c, int l) {
    float d0a[4] = {0.f,0.f,0.f,0.f}, d0b[4] = {0.f,0.f,0.f,0.f};
    float d1a[4] = {0.f,0.f,0.f,0.f}, d1b[4] = {0.f,0.f,0.f,0.f};
    #pragma unroll
    for (int kt = 0; kt < 8; ++kt) {
        unsigned b0[2], b1[2];
        b0[0] = *(const unsigned*)&e_h[16 * kt + c];
        b0[1] = *(const unsigned*)&e_h[16 * kt + c + 8];
        b1[0] = *(const unsigned*)&e_h[16 * (kt + 8) + c];
        b1[1] = *(const unsigned*)&e_h[16 * (kt + 8) + c + 8];
        mma16816(d0a, Af[0][kt], b0);
        mma16816(d1a, Af[1][kt], b0);
        mma16816(d0b, Af[0][kt + 8], b1);
        mma16816(d1b, Af[1][kt + 8], b1);
    }
    if ((l & 3) == 0) {
        newv[32 * w + r]      = d0a[0] + d0b[0];
        newv[32 * w + r + 8]  = d0a[2] + d0b[2];
        newv[32 * w + 16 + r] = d1a[0] + d1b[0];
        newv[32 * w + 24 + r] = d1a[2] + d1b[2];
    }
}

// Tensor-core scan: one CTA per (n, dir). Matrix in A-fragments (regs) for all
// 255 steps. Per step: redux-based max (1 bar) + HMMA (1 bar) + combine (1 bar).
__global__ void __launch_bounds__(256) scan_kernel() {
    __shared__ __half e_h[CC];
    __shared__ float newv[CC];
    __shared__ unsigned redu[8];
    const int bx = blockIdx.x;
    const bool fwd = bx < 8;
    const int n = fwd ? bx : bx - 8;
    const int tid = threadIdx.x;
    const int w = tid >> 5, l = tid & 31;
    const int r = l >> 2, c = (l & 3) * 2;
    const float* M = fwd ? g_bwdM : g_fwdM;  // [row=output][col=summed]

    unsigned Af[2][16][4];
    #pragma unroll
    for (int rt = 0; rt < 2; ++rt) {
        #pragma unroll
        for (int kt = 0; kt < 16; ++kt) {
            int R = 32 * w + 16 * rt + r;
            int K = 16 * kt + c;
            float2 v00 = *(const float2*)(M + R * 256 + K);
            float2 v10 = *(const float2*)(M + (R + 8) * 256 + K);
            float2 v01 = *(const float2*)(M + R * 256 + K + 8);
            float2 v11 = *(const float2*)(M + (R + 8) * 256 + K + 8);
            Af[rt][kt][0] = pack_h2(v00.x, v00.y);
            Af[rt][kt][1] = pack_h2(v10.x, v10.y);
            Af[rt][kt][2] = pack_h2(v01.x, v01.y);
            Af[rt][kt][3] = pack_h2(v11.x, v11.y);
        }
    }
    __syncthreads();

    if (fwd) {
        float alpha = 0.f;
        for (int t = 0; t < TM1; ++t) {
            float obs_next = g_obs[(n * TT + t + 1) * CC + tid];
            float v = (t == 0) ? (g_init[tid] + g_obs[(n * TT) * CC + tid]) : alpha;
            float m = blockMaxFast(v, redu);           // barrier 1
            e_h[tid] = __float2half(__expf(v - m));
            __syncthreads();                           // barrier 2
            mma_step(Af, e_h, newv, w, r, c, l);
            __syncthreads();                           // barrier 3
            alpha = m + __logf(newv[tid]) + obs_next;
            g_alphas[(t * NB + n) * CC + tid] = alpha;
        }
    } else {
        float carry = 0.f;
        for (int t = TM1 - 1; t >= 0; --t) {
            g_betas[(t * NB + n) * CC + tid] = carry;
            if (t == 0) break;
            float wv = g_obs[(n * TT + t + 1) * CC + tid] + carry;
            float m = blockMaxFast(wv, redu);          // barrier 1
            e_h[tid] = __float2half(__expf(wv - m));
            __syncthreads();                           // barrier 2
            mma_step(Af, e_h, newv, w, r, c, l);
            __syncthreads();                           // barrier 3
            carry = m + __logf(newv[tid]);
        }
    }
}

__global__ void logz_ev_kernel(const int* __restrict__ lengths) {
    __shared__ float red[8];
    float ev = 0.f;
    for (int n = 0; n < NB; ++n) {
        float v = g_alphas[((TM1 - 1) * NB + n) * CC + threadIdx.x];
        float m = blockMax256(v, red);
        float s = blockSum256(__expf(v - m), red);
        if (threadIdx.x == 0) g_logZ[n] = m + __logf(s);
        int ti = lengths[n] - 1;
        if (ti < 0) ti = 0;
        if (ti > TM1 - 1) ti = TM1 - 1;
        float v2 = g_alphas[(ti * NB + n) * CC + threadIdx.x];
        float m2 = blockMax256(v2, red);
        float s2 = blockSum256(__expf(v2 - m2), red);
        ev += m2 + __logf(s2);
    }
    if (threadIdx.x == 0) g_evidence = ev;
}

#define ELBO_SMEM ((64 * 256 + 256 + 256 + 64 + 64 + 8) * 4)
__global__ void __launch_bounds__(256) elbo_kernel() {
    extern __shared__ float smf[];
    float* Ts   = smf;
    float* vb   = Ts + 64 * 256;
    float* t0b  = vb + 256;
    float* obsA = t0b + 256;
    float* wa   = obsA + 64;
    float* red  = wa + 64;
    const int n = blockIdx.z;
    const int a0 = blockIdx.y * 64;
    const int tb = blockIdx.x * 8;
    const int b = threadIdx.x;

    for (int i = threadIdx.x; i < 64 * 256; i += 256)
        Ts[i] = g_trans[(a0 + (i >> 8)) * CC + (i & 255)];
    const float lz = g_logZ[n];
    float local = 0.f;

    for (int tt = 0; tt < 8; ++tt) {
        int t = tb + tt;
        if (t >= TM1) break;
        __syncthreads();
        float tz = (t == 0) ? (g_init[b] + g_obs[(n * TT) * CC + b]) : 0.f;
        float ap = (t == 0) ? 0.f : g_alphas[((t - 1) * NB + n) * CC + b];
        t0b[b] = tz;
        vb[b]  = ap + tz - lz;
        if (b < 64) {
            int a = a0 + b;
            float oa = g_obs[(n * TT + t + 1) * CC + a];
            obsA[b] = oa;
            wa[b] = g_betas[(t * NB + n) * CC + a] + oa;
        }
        __syncthreads();
        float vbb = vb[b], tzb = t0b[b];
        #pragma unroll 8
        for (int al = 0; al < 64; ++al) {
            float tr = Ts[al * 256 + b];
            float L  = tr + wa[al] + vbb;
            float ph = tr + obsA[al] + tzb;
            local += __expf(L) * ph;
        }
    }
    __syncthreads();
    float s = blockSum256(local, red);
    if (threadIdx.x == 0)
        g_partials[(blockIdx.z * 4 + blockIdx.y) * 32 + blockIdx.x] = s;
}

__global__ void finalize_kernel(float* __restrict__ out) {
    __shared__ float red[8];
    float s = 0.f;
    for (int i = threadIdx.x; i < 1024; i += 256) s += g_partials[i];
    s = blockSum256(s, red);
    if (threadIdx.x == 0) { out[0] = s; out[1] = g_evidence; }
}

extern "C" void kernel_launch(void* const* d_in, const int* in_sizes, int n_in,
                              void* d_out, int out_size) {
    const int*   text      = (const int*)d_in[0];
    const int*   lengths   = (const int*)d_in[2];
    const float* start_emb = (const float*)d_in[3];
    const float* state_emb = (const float*)d_in[4];
    const float* pre_emb   = (const float*)d_in[5];
    const float* sw1 = (const float*)d_in[6];
    const float* sb1 = (const float*)d_in[7];
    const float* sw2 = (const float*)d_in[8];
    const float* sb2 = (const float*)d_in[9];
    const float* sw3 = (const float*)d_in[10];
    const float* sb3 = (const float*)d_in[11];
    const float* tw1 = (const float*)d_in[12];
    const float* tb1 = (const float*)d_in[13];
    const float* tw2 = (const float*)d_in[14];
    const float* tb2 = (const float*)d_in[15];
    const float* tw3 = (const float*)d_in[16];
    const float* tb3 = (const float*)d_in[17];
    const float* ew1 = (const float*)d_in[18];
    const float* eb1 = (const float*)d_in[19];
    const float* ew2 = (const float*)d_in[20];
    const float* eb2 = (const float*)d_in[21];
    const float* ew3 = (const float*)d_in[22];
    const float* eb3 = (const float*)d_in[23];
    float* out = (float*)d_out;

    cudaFuncSetAttribute(elbo_kernel, cudaFuncAttributeMaxDynamicSharedMemorySize, ELBO_SMEM);

    // launch 0: layer1 of start/trans/term nets
    gemmL1_kernel<<<dim3(4, 4, 3), 256>>>(start_emb, state_emb, pre_emb,
                                          sw1, tw1, ew1, sb1, tb1, eb1);
    // launch 1: layer2 (relu + residual)
    gemmL2_kernel<<<dim3(4, 4, 3), 256>>>(start_emb, state_emb, pre_emb,
                                          sw2, tw2, ew2, sb2, tb2, eb2);
    // launch 2: heads (term GEMM + trans GEMM + start gemv)
    heads_kernel<<<dim3(157, 4, 3), 256>>>(tw3, tb3, ew3, eb3, sw3, sb3);
    // launch 3: fused softmaxes + obs gather
    prep_kernel<<<513, 256>>>(text);
    // launch 4: tensor-core forward/backward scans
    scan_kernel<<<16, 256>>>();
    // launch 5: logZ + evidence
    logz_ev_kernel<<<1, 256>>>(lengths);
    // launch 6: elbo accumulation
    elbo_kernel<<<dim3(32, 4, 8), 256, ELBO_SMEM>>>();
    // launch 7: final reduction
    finalize_kernel<<<1, 256>>>(out);
}